// round 10
// baseline (speedup 1.0000x reference)
#include <cuda_runtime.h>
#include <cstdint>

// ---------------------------------------------------------------------------
// FAME_GCN. R10: cp.async.bulk (TMA-engine) streaming. 256-thr CTA holds a
// DEPTH=8 x 16KB ring of raw plane tiles permanently in flight (~128KB/SM
// outstanding vs ~8-16KB on the LDG path that pinned every prior round at
// ~33% DRAM). Merge folds planes into register accumulators on arrival.
// Persistent (column, 20-tile band) CTAs; dual-direction SpMM; bulk-reduce.
// ---------------------------------------------------------------------------

constexpr int N_NODES = 5000, NFEAT = 128, OUTC = 16, TILE = 64;
constexpr int NT     = (N_NODES + TILE - 1) / TILE;     // 79
constexpr int NTHR   = 256, DEPTH = 8, BANDT = 20;
constexpr int NBANDS = (NT + BANDT - 1) / BANDT;        // 4
// smem layout (float offsets)
constexpr int OF_RING = 0;                    // DEPTH * 4096
constexpr int OF_P    = OF_RING + DEPTH * 4096;
constexpr int OF_SC   = OF_P + 4096;
constexpr int OF_SR   = OF_SC + 1024;
constexpr int OF_ST   = OF_SR + 1024;         // 2 x 2048 stage bufs
constexpr int OF_MB   = OF_ST + 4096;         // 8 mbarriers (u64)
constexpr int SMEM_BYTES = (OF_MB + 16) * 4;  // 172,096 B

__device__ float g_s0[N_NODES * OUTC];
__device__ float g_s1[N_NODES * OUTC];
__device__ float g_acc0[N_NODES * OUTC];
__device__ float g_acc1[N_NODES * OUTC];

// ------------------------- PTX helpers -------------------------------------
__device__ __forceinline__ double pack2(float lo, float hi) {
    double d; asm("mov.b64 %0, {%1, %2};" : "=d"(d) : "f"(lo), "f"(hi)); return d;
}
__device__ __forceinline__ double ffma2(double a, double b, double c) {
    double d; asm("fma.rn.f32x2 %0, %1, %2, %3;" : "=d"(d) : "d"(a), "d"(b), "d"(c));
    return d;
}
__device__ __forceinline__ void mb_init(uint32_t mb, uint32_t cnt) {
    asm volatile("mbarrier.init.shared.b64 [%0], %1;" :: "r"(mb), "r"(cnt) : "memory");
}
__device__ __forceinline__ void mb_expect(uint32_t mb, uint32_t bytes) {
    asm volatile("mbarrier.arrive.expect_tx.shared.b64 _, [%0], %1;"
                 :: "r"(mb), "r"(bytes) : "memory");
}
__device__ __forceinline__ void mb_wait(uint32_t mb, uint32_t par) {
    asm volatile("{\n\t.reg .pred p;\n\tWL%=:\n\t"
                 "mbarrier.try_wait.parity.shared.b64 p, [%0], %1, 0x989680;\n\t"
                 "@!p bra WL%=;\n\t}" :: "r"(mb), "r"(par) : "memory");
}
__device__ __forceinline__ void blk_cp(uint32_t dst, const float* src,
                                       uint32_t bytes, uint32_t mb) {
    asm volatile("cp.async.bulk.shared::cta.global.mbarrier::complete_tx::bytes "
                 "[%0], [%1], %2, [%3];"
                 :: "r"(dst), "l"(src), "r"(bytes), "r"(mb) : "memory");
}

// ------------------------- prep --------------------------------------------
__global__ void __launch_bounds__(256) prep_kernel(const float* __restrict__ feature,
                                                   const float* __restrict__ W3,
                                                   const float* __restrict__ W1) {
    __shared__ float Ws[2 * NFEAT * OUTC];
    int t = threadIdx.x;
    for (int q = t; q < NFEAT * OUTC; q += 256) {
        Ws[q] = W3[q]; Ws[NFEAT * OUTC + q] = W1[q];
    }
    __syncthreads();
    int gid = blockIdx.x * 256 + t, stride = gridDim.x * 256;
    for (int q = gid; q < N_NODES * OUTC; q += stride) { g_acc0[q] = 0.f; g_acc1[q] = 0.f; }
    for (int u = gid; u < 2 * N_NODES * 4; u += stride) {
        int which = (u >= N_NODES * 4) ? 1 : 0;
        int rem = u - which * (N_NODES * 4);
        int i = rem >> 2, q4 = rem & 3;
        const float4* f4 = (const float4*)(feature + (size_t)i * NFEAT);
        const float4* W4 = (const float4*)(Ws + which * (NFEAT * OUTC));
        float a0 = 0.f, a1 = 0.f, a2 = 0.f, a3 = 0.f;
        #pragma unroll 8
        for (int k4 = 0; k4 < NFEAT / 4; ++k4) {
            float4 f = f4[k4];
            float4 w0 = W4[(4 * k4 + 0) * 4 + q4], w1 = W4[(4 * k4 + 1) * 4 + q4];
            float4 w2 = W4[(4 * k4 + 2) * 4 + q4], w3 = W4[(4 * k4 + 3) * 4 + q4];
            a0 = fmaf(f.x, w0.x, a0); a1 = fmaf(f.x, w0.y, a1);
            a2 = fmaf(f.x, w0.z, a2); a3 = fmaf(f.x, w0.w, a3);
            a0 = fmaf(f.y, w1.x, a0); a1 = fmaf(f.y, w1.y, a1);
            a2 = fmaf(f.y, w1.z, a2); a3 = fmaf(f.y, w1.w, a3);
            a0 = fmaf(f.z, w2.x, a0); a1 = fmaf(f.z, w2.y, a1);
            a2 = fmaf(f.z, w2.z, a2); a3 = fmaf(f.z, w2.w, a3);
            a0 = fmaf(f.w, w3.x, a0); a1 = fmaf(f.w, w3.y, a1);
            a2 = fmaf(f.w, w3.z, a2); a3 = fmaf(f.w, w3.w, a3);
        }
        float* dst = (which ? g_s1 : g_s0) + (size_t)i * OUTC + q4 * 4;
        *(float4*)dst = make_float4(a0, a1, a2, a3);
    }
}

// ------------------------- band body ---------------------------------------
template<int K>
__device__ void band_body(float* sm, uint32_t sm_u,
                          const float* __restrict__ A, const float* __restrict__ w,
                          const float* __restrict__ s, float* __restrict__ acc,
                          int ct, int band) {
    const size_t NN = (size_t)N_NODES * N_NODES;
    float4* ring = (float4*)(sm + OF_RING);
    float4* P4   = (float4*)(sm + OF_P);
    float*  sC   = sm + OF_SC;
    float*  sR   = sm + OF_SR;
    uint32_t ring_u = sm_u + OF_RING * 4;
    uint32_t mb_u   = sm_u + OF_MB * 4;

    int tid = threadIdx.x;
    int rt0 = band * BANDT;
    int ntiles = min(BANDT, NT - rt0);
    int NU = ntiles * K;
    int gc0 = ct * TILE;
    int cv4 = min(16, (N_NODES - gc0 + 3) / 4);   // valid chunk cols

    float wk[K];
    #pragma unroll
    for (int k = 0; k < K; ++k) wk[k] = w[k];

    if (tid == 0) {
        #pragma unroll
        for (int i = 0; i < DEPTH; ++i) mb_init(mb_u + i * 8, 1);
    }
    // sC: fixed column block (one float4 per thread)
    {
        int j = tid >> 2, p = tid & 3, gj = gc0 + j;
        float4 v = make_float4(0.f, 0.f, 0.f, 0.f);
        if (gj < N_NODES) v = ((const float4*)s)[gj * 4 + p];
        ((float4*)sC)[tid] = v;
    }
    __syncthreads();

    auto issue = [&](int u) {   // warp 0 only
        int t = u / K, k = u - t * K;
        int gr0 = (rt0 + t) * TILE;
        int rv = min(TILE, N_NODES - gr0);
        const float* plane = A + (size_t)k * NN + (size_t)gr0 * N_NODES + gc0;
        uint32_t slot = ring_u + (u % DEPTH) * 16384;
        uint32_t mb   = mb_u + (u % DEPTH) * 8;
        if (tid == 0) mb_expect(mb, (uint32_t)(rv * cv4 * 16));
        __syncwarp();
        int lane = tid;
        #pragma unroll
        for (int it = 0; it < 2; ++it) {
            int r = lane + it * 32;
            if (r < rv)
                blk_cp(slot + r * 256, plane + (size_t)r * N_NODES, cv4 * 16, mb);
        }
    };
    if (tid < 32)
        for (int u = 0; u < DEPTH; ++u) issue(u);   // prologue (NU >= 57)

    int buf = 0;
    for (int t = 0; t < ntiles; ++t) {
        int gr0 = (rt0 + t) * TILE;
        int rv = min(TILE, N_NODES - gr0);

        // merge K planes into register accumulators (4 owned chunks)
        float4 pacc[4];
        #pragma unroll
        for (int i = 0; i < 4; ++i) pacc[i] = make_float4(0.f, 0.f, 0.f, 0.f);
        for (int k = 0; k < K; ++k) {
            int u = t * K + k;
            mb_wait(mb_u + (u % DEPTH) * 8, (u / DEPTH) & 1);
            const float4* slot = ring + (u % DEPTH) * 1024;
            float wkv = wk[k];
            #pragma unroll
            for (int i = 0; i < 4; ++i) {
                int c = tid + i * 256;
                if ((c >> 4) < rv && (c & 15) < cv4) {
                    float4 v = slot[c];
                    pacc[i].x = fmaf(wkv, v.x, pacc[i].x);
                    pacc[i].y = fmaf(wkv, v.y, pacc[i].y);
                    pacc[i].z = fmaf(wkv, v.z, pacc[i].z);
                    pacc[i].w = fmaf(wkv, v.w, pacc[i].w);
                }
            }
            __syncthreads();                       // slot consumed by all
            if (tid < 32 && u + DEPTH < NU) issue(u + DEPTH);
        }
        // publish P (XOR swizzle) + sR; guard stage buf reuse
        #pragma unroll
        for (int i = 0; i < 4; ++i) {
            int c = tid + i * 256, row = c >> 4;
            P4[(row << 4) | ((c & 15) ^ (row & 15))] = pacc[i];
        }
        {
            int j = tid >> 2, p = tid & 3, gj = gr0 + j;
            float4 v = make_float4(0.f, 0.f, 0.f, 0.f);
            if (gj < N_NODES) v = ((const float4*)s)[gj * 4 + p];
            ((float4*)sR)[tid] = v;
        }
        if (tid == 0)
            asm volatile("cp.async.bulk.wait_group 1;" ::: "memory");
        __syncthreads();

        double* stR = (double*)(sm + OF_ST + buf * 2048);
        double* stC = stR + 512;
        if (tid < 128) {   // row pass: rows 4rg..4rg+3, ch-pair chg
            int rg = tid & 15, chg = tid >> 4;
            double ra[4] = {0.0, 0.0, 0.0, 0.0};
            const double* sd = (const double*)sC;
            #pragma unroll 2
            for (int jb = 0; jb < 16; ++jb) {
                double s0 = sd[(4 * jb + 0) * 8 + chg], s1 = sd[(4 * jb + 1) * 8 + chg];
                double s2 = sd[(4 * jb + 2) * 8 + chg], s3 = sd[(4 * jb + 3) * 8 + chg];
                #pragma unroll
                for (int i = 0; i < 4; ++i) {
                    int r = 4 * rg + i;
                    float4 m = P4[(r << 4) | (jb ^ (r & 15))];
                    ra[i] = ffma2(pack2(m.x, m.x), s0, ra[i]);
                    ra[i] = ffma2(pack2(m.y, m.y), s1, ra[i]);
                    ra[i] = ffma2(pack2(m.z, m.z), s2, ra[i]);
                    ra[i] = ffma2(pack2(m.w, m.w), s3, ra[i]);
                }
            }
            #pragma unroll
            for (int i = 0; i < 4; ++i) stR[(4 * rg + i) * 8 + chg] = ra[i];
        } else {           // col pass: cols 4cg..4cg+3, ch-pair chg
            int tt = tid - 128, cg = tt & 15, chg = tt >> 4;
            double ca[4] = {0.0, 0.0, 0.0, 0.0};
            #pragma unroll 2
            for (int i = 0; i < TILE; ++i) {
                float4 m = P4[(i << 4) | (cg ^ (i & 15))];
                double sv = *(const double*)(sR + i * OUTC + 2 * chg);
                ca[0] = ffma2(pack2(m.x, m.x), sv, ca[0]);
                ca[1] = ffma2(pack2(m.y, m.y), sv, ca[1]);
                ca[2] = ffma2(pack2(m.z, m.z), sv, ca[2]);
                ca[3] = ffma2(pack2(m.w, m.w), sv, ca[3]);
            }
            #pragma unroll
            for (int q = 0; q < 4; ++q) stC[(4 * cg + q) * 8 + chg] = ca[q];
        }
        __syncthreads();

        if (tid == 0) {
            asm volatile("fence.proxy.async.shared::cta;" ::: "memory");
            int cv = min(TILE, N_NODES - gc0);
            uint32_t srR = sm_u + (OF_ST + buf * 2048) * 4;
            asm volatile(
                "cp.reduce.async.bulk.global.shared::cta.bulk_group.add.f32 [%0], [%1], %2;"
                :: "l"(acc + (size_t)gr0 * OUTC), "r"(srR), "r"(rv * OUTC * 4) : "memory");
            asm volatile(
                "cp.reduce.async.bulk.global.shared::cta.bulk_group.add.f32 [%0], [%1], %2;"
                :: "l"(acc + (size_t)gc0 * OUTC), "r"(srR + 4096), "r"(cv * OUTC * 4) : "memory");
            asm volatile("cp.async.bulk.commit_group;" ::: "memory");
        }
        buf ^= 1;
        __syncthreads();   // stage writes of next tile must not pass flush issue
    }
    if (tid == 0)
        asm volatile("cp.async.bulk.wait_group 0;" ::: "memory");
}

__global__ void __launch_bounds__(NTHR, 1)
mm_kernel(const float* __restrict__ A3, const float* __restrict__ w3,
          const float* __restrict__ A9, const float* __restrict__ w9) {
    extern __shared__ __align__(16) float sm[];
    uint32_t sm_u = (uint32_t)__cvta_generic_to_shared(sm);
    int grp = blockIdx.x & 1, ct = blockIdx.x >> 1, band = blockIdx.y;
    if (grp == 0) band_body<3>(sm, sm_u, A3, w3, g_s0, g_acc0, ct, band);
    else          band_body<9>(sm, sm_u, A9, w9, g_s1, g_acc1, ct, band);
}

// ------------------------- finalize ----------------------------------------
__global__ void __launch_bounds__(256) finalize_kernel(const float* __restrict__ b3,
                                                       const float* __restrict__ b1,
                                                       float* __restrict__ out) {
    int gid = blockIdx.x * 256 + threadIdx.x;
    if (gid < N_NODES * 2 * OUTC) {
        int i = gid >> 5, c = gid & 31;
        float v;
        if (c < OUTC) v = g_acc0[i * OUTC + c] + b3[c];
        else          v = g_acc1[i * OUTC + (c - OUTC)] + b1[c - OUTC];
        out[gid] = v;
    }
}

// ------------------------- launch ------------------------------------------
extern "C" void kernel_launch(void* const* d_in, const int* in_sizes, int n_in,
                              void* d_out, int out_size) {
    const float* feature = (const float*)d_in[0];
    const float* A       = (const float*)d_in[1];
    const float* A_t     = (const float*)d_in[2];
    const float* w2      = (const float*)d_in[3];
    const float* wb      = (const float*)d_in[4];
    const float* W3      = (const float*)d_in[5];
    const float* b3      = (const float*)d_in[6];
    const float* W1      = (const float*)d_in[7];
    const float* b1      = (const float*)d_in[8];
    float* out = (float*)d_out;

    static int attr_done = 0;
    if (!attr_done) {
        cudaFuncSetAttribute(mm_kernel,
                             cudaFuncAttributeMaxDynamicSharedMemorySize, SMEM_BYTES);
        cudaFuncSetAttribute(mm_kernel,
                             cudaFuncAttributePreferredSharedMemoryCarveout,
                             cudaSharedmemCarveoutMaxShared);
        attr_done = 1;
    }

    prep_kernel<<<640, 256>>>(feature, W3, W1);

    dim3 grid(2 * NT, NBANDS);
    mm_kernel<<<grid, NTHR, SMEM_BYTES>>>(A, w2, A_t, wb);

    finalize_kernel<<<(N_NODES * 2 * OUTC + 255) / 256, 256>>>(b3, b1, out);
}

// round 11
// speedup vs baseline: 3.5628x; 3.5628x over previous
#include <cuda_runtime.h>
#include <cstdint>

// ---------------------------------------------------------------------------
// FAME_GCN: out = concat( (T3 + T3^T) @ (feature@W3) + b3,
//                         (T9 + T9^T) @ (feature@W1) + b1 )
// with T3 = sum_k weight_b2[k] * A[k],  T9 = sum_k weight_b[k] * A_t[k].
//
// R11 = R3 (best, 324us) with the contended cp.reduce.async.bulk + wait_group
// flush replaced by EXCLUSIVE-SLOT plain STG partials (no atomics, no waits,
// CTA exits straight from SpMM registers). Theory: the per-CTA blocked flush
// into contended g_acc was throttling DRAM duty to ~33% in every round.
// finalize does the 158-way partial reduction (+101MB traffic, ~25us).
// ---------------------------------------------------------------------------

constexpr int N_NODES  = 5000;
constexpr int NFEAT    = 128;
constexpr int OUTC     = 16;
constexpr int TILE     = 64;
constexpr int PJ       = TILE + 1;                      // 65: odd pitch -> conflict-free
constexpr int NT       = (N_NODES + TILE - 1) / TILE;   // 79
constexpr int NTHREADS = 2 * TILE;                      // 128
constexpr int SLOTS    = TILE * (TILE / 4);             // 1024 float4 slots

// static scratch (no allocation allowed). Partials: exclusive slot per CTA,
// every element written exactly once per run -> no zero-init needed.
__device__ float g_s0[N_NODES * OUTC];                  // feature @ W3
__device__ float g_s1[N_NODES * OUTC];                  // feature @ W1
__device__ float g_rp0[(size_t)NT * N_NODES * OUTC];    // row partials, group 0
__device__ float g_cp0[(size_t)NT * N_NODES * OUTC];    // col partials, group 0
__device__ float g_rp1[(size_t)NT * N_NODES * OUTC];    // row partials, group 1
__device__ float g_cp1[(size_t)NT * N_NODES * OUTC];    // col partials, group 1

// ------------------------- PTX helpers -------------------------------------

__device__ __forceinline__ double pack2(float lo, float hi) {
    double d;
    asm("mov.b64 %0, {%1, %2};" : "=d"(d) : "f"(lo), "f"(hi));
    return d;
}

// packed 2-wide fp32 FMA — 2x scalar FFMA throughput on sm_103a
__device__ __forceinline__ double ffma2(double a, double b, double c) {
    double d;
    asm("fma.rn.f32x2 %0, %1, %2, %3;" : "=d"(d) : "d"(a), "d"(b), "d"(c));
    return d;
}

// ------------------------- prep: support GEMMs -----------------------------

__global__ void __launch_bounds__(256) prep_kernel(const float* __restrict__ feature,
                                                   const float* __restrict__ W3,
                                                   const float* __restrict__ W1) {
    __shared__ float Ws[2 * NFEAT * OUTC];   // 16 KB
    int t = threadIdx.x;
    for (int q = t; q < NFEAT * OUTC; q += 256) {
        Ws[q] = W3[q];
        Ws[NFEAT * OUTC + q] = W1[q];
    }
    __syncthreads();

    int gid    = blockIdx.x * 256 + t;
    int stride = gridDim.x * 256;

    for (int row = gid; row < 2 * N_NODES; row += stride) {
        int which = (row >= N_NODES) ? 1 : 0;
        int i = which ? row - N_NODES : row;
        const float4* f4 = (const float4*)(feature + (size_t)i * NFEAT);
        const float* Wp = Ws + which * (NFEAT * OUTC);
        float a[OUTC];
        #pragma unroll
        for (int c = 0; c < OUTC; ++c) a[c] = 0.f;
        #pragma unroll 4
        for (int k4 = 0; k4 < NFEAT / 4; ++k4) {
            float4 f = f4[k4];
            const float* w0 = Wp + (k4 * 4) * OUTC;
            #pragma unroll
            for (int c = 0; c < OUTC; ++c) {
                float v = fmaf(f.x, w0[c], 0.f);
                v = fmaf(f.y, w0[OUTC + c], v);
                v = fmaf(f.z, w0[2 * OUTC + c], v);
                v = fmaf(f.w, w0[3 * OUTC + c], v);
                a[c] += v;
            }
        }
        float* dst = (which ? g_s1 : g_s0) + (size_t)i * OUTC;
        #pragma unroll
        for (int c = 0; c < OUTC; ++c) dst[c] = a[c];
    }
}

// ------------------------- fused merge + dual SpMM body --------------------

template<int K>
__device__ __forceinline__ void mm_tile(float* __restrict__ P,
                                        float* __restrict__ sC,
                                        float* __restrict__ sR,
                                        const float* __restrict__ A,
                                        const float* __restrict__ w,
                                        const float* __restrict__ s,
                                        float* __restrict__ rp,   // row partials
                                        float* __restrict__ cp,   // col partials
                                        int r, int c) {
    int t   = threadIdx.x;
    int gr0 = r * TILE, gc0 = c * TILE;

    float wk[K];
    #pragma unroll
    for (int k = 0; k < K; ++k) wk[k] = w[k];

    // load s tiles (zero-padded at edge): 512 float4 slots / 128 threads
    {
        const float4* s4 = (const float4*)s;
        #pragma unroll
        for (int it = 0; it < (2 * TILE * OUTC / 4) / NTHREADS; ++it) {
            int q    = t + it * NTHREADS;     // 0..511
            int half = q >> 8;                // 0 -> sC, 1 -> sR
            int qq   = q & 255;
            int j    = qq >> 2, p = qq & 3;
            int gj   = (half ? gr0 : gc0) + j;
            float4 v = make_float4(0.f, 0.f, 0.f, 0.f);
            if (gj < N_NODES) v = s4[gj * 4 + p];
            ((float4*)(half ? sR : sC))[qq] = v;
        }
    }

    // load + merge adjacency tile (each global element touched exactly once)
    {
        const size_t NN = (size_t)N_NODES * N_NODES;
        #pragma unroll
        for (int it = 0; it < SLOTS / NTHREADS; ++it) {   // 8 iters
            int q   = t + it * NTHREADS;
            int row = q >> 4;
            int col = (q & 15) * 4;
            int gr = gr0 + row, gc = gc0 + col;
            float4 a = make_float4(0.f, 0.f, 0.f, 0.f);
            if (gr < N_NODES && gc < N_NODES) {           // N%4==0: f4 fully valid
                const float* p = A + (size_t)gr * N_NODES + gc;
                #pragma unroll
                for (int k = 0; k < K; ++k) {
                    float4 v = *(const float4*)(p + (size_t)k * NN);
                    a.x = fmaf(wk[k], v.x, a.x);
                    a.y = fmaf(wk[k], v.y, a.y);
                    a.z = fmaf(wk[k], v.z, a.z);
                    a.w = fmaf(wk[k], v.w, a.w);
                }
            }
            float* d = P + row * PJ + col;
            d[0] = a.x; d[1] = a.y; d[2] = a.z; d[3] = a.w;
        }
    }
    __syncthreads();

    // dual SpMM: threads 0..63 row pass (out rows gr0+t),
    //            threads 64..127 col pass (out cols gc0+(t-64)).
    double vacc[8];
    #pragma unroll
    for (int q = 0; q < 8; ++q) vacc[q] = 0.0;            // bits = (0.f,0.f)

    const float* mp;
    int mstride;
    const float* sv;
    if (t < TILE) { mp = P + t * PJ;      mstride = 1;  sv = sC; }
    else          { mp = P + (t - TILE);  mstride = PJ; sv = sR; }

    #pragma unroll 4
    for (int j = 0; j < TILE; ++j) {
        float m = mp[j * mstride];
        double mm = pack2(m, m);
        const double2* s2 = (const double2*)(sv + j * OUTC);   // broadcast loads
        double2 a0 = s2[0], a1 = s2[1], a2 = s2[2], a3 = s2[3];
        vacc[0] = ffma2(mm, a0.x, vacc[0]);
        vacc[1] = ffma2(mm, a0.y, vacc[1]);
        vacc[2] = ffma2(mm, a1.x, vacc[2]);
        vacc[3] = ffma2(mm, a1.y, vacc[3]);
        vacc[4] = ffma2(mm, a2.x, vacc[4]);
        vacc[5] = ffma2(mm, a2.y, vacc[5]);
        vacc[6] = ffma2(mm, a3.x, vacc[6]);
        vacc[7] = ffma2(mm, a3.y, vacc[7]);
    }

    // direct exclusive-slot store: no staging, no atomics, no waits
    if (t < TILE) {
        int grow = gr0 + t;
        if (grow < N_NODES) {
            float4* d = (float4*)(rp + ((size_t)c * N_NODES + grow) * OUTC);
            d[0] = *(float4*)&vacc[0];
            d[1] = *(float4*)&vacc[2];
            d[2] = *(float4*)&vacc[4];
            d[3] = *(float4*)&vacc[6];
        }
    } else {
        int gcol = gc0 + (t - TILE);
        if (gcol < N_NODES) {
            float4* d = (float4*)(cp + ((size_t)r * N_NODES + gcol) * OUTC);
            d[0] = *(float4*)&vacc[0];
            d[1] = *(float4*)&vacc[2];
            d[2] = *(float4*)&vacc[4];
            d[3] = *(float4*)&vacc[6];
        }
    }
}

// Fused kernel: grid.x interleaves group 0 (K=3, A) and group 1 (K=9, A_t)
__global__ void __launch_bounds__(NTHREADS) mm_combined(const float* __restrict__ A3,
                                                        const float* __restrict__ w3,
                                                        const float* __restrict__ A9,
                                                        const float* __restrict__ w9) {
    __shared__ __align__(16) float P[TILE * PJ];
    __shared__ __align__(16) float sC[TILE * OUTC];
    __shared__ __align__(16) float sR[TILE * OUTC];

    int grp = blockIdx.x & 1;
    int c   = blockIdx.x >> 1;
    int r   = blockIdx.y;

    if (grp == 0) mm_tile<3>(P, sC, sR, A3, w3, g_s0, g_rp0, g_cp0, r, c);
    else          mm_tile<9>(P, sC, sR, A9, w9, g_s1, g_rp1, g_cp1, r, c);
}

// ------------- finalize: 158-way partial reduce + bias + concat ------------
// thread owns (node i, quarter q of one group's 16 channels)

__global__ void __launch_bounds__(256) finalize_kernel(const float* __restrict__ b3,
                                                       const float* __restrict__ b1,
                                                       float* __restrict__ out) {
    int gid = blockIdx.x * 256 + threadIdx.x;        // 0 .. 5000*8-1
    if (gid >= N_NODES * 8) return;
    int i   = gid >> 3;
    int q   = gid & 7;
    int grp = q >> 2;                                // 0: ch 0-15, 1: ch 16-31
    int q4  = q & 3;                                 // float4 within the 16 ch

    const float4* rp = (const float4*)(grp ? g_rp1 : g_rp0);
    const float4* cpp = (const float4*)(grp ? g_cp1 : g_cp0);
    size_t base = (size_t)i * 4 + q4;
    size_t slotstride = (size_t)N_NODES * 4;

    float4 acc = make_float4(0.f, 0.f, 0.f, 0.f);
    #pragma unroll 4
    for (int sl = 0; sl < NT; ++sl) {
        float4 a = rp[base + (size_t)sl * slotstride];
        float4 b = cpp[base + (size_t)sl * slotstride];
        acc.x += a.x + b.x; acc.y += a.y + b.y;
        acc.z += a.z + b.z; acc.w += a.w + b.w;
    }
    const float* bias = grp ? b1 : b3;
    acc.x += bias[q4 * 4 + 0];
    acc.y += bias[q4 * 4 + 1];
    acc.z += bias[q4 * 4 + 2];
    acc.w += bias[q4 * 4 + 3];

    *(float4*)(out + (size_t)i * 32 + grp * 16 + q4 * 4) = acc;
}

// ------------------------- launch ------------------------------------------

extern "C" void kernel_launch(void* const* d_in, const int* in_sizes, int n_in,
                              void* d_out, int out_size) {
    const float* feature = (const float*)d_in[0];
    const float* A       = (const float*)d_in[1];
    const float* A_t     = (const float*)d_in[2];
    const float* w2      = (const float*)d_in[3];   // weight_b2 [3,1]
    const float* wb      = (const float*)d_in[4];   // weight_b  [9,1]
    const float* W3      = (const float*)d_in[5];
    const float* b3      = (const float*)d_in[6];
    const float* W1      = (const float*)d_in[7];
    const float* b1      = (const float*)d_in[8];
    float* out = (float*)d_out;

    static int attr_done = 0;
    if (!attr_done) {
        cudaFuncSetAttribute(mm_combined,
                             cudaFuncAttributePreferredSharedMemoryCarveout,
                             cudaSharedmemCarveoutMaxShared);
        attr_done = 1;   // attribute is sticky; not a work-caching guard
    }

    prep_kernel<<<160, 256>>>(feature, W3, W1);

    dim3 grid(2 * NT, NT);
    mm_combined<<<grid, NTHREADS>>>(A, w2, A_t, wb);

    finalize_kernel<<<(N_NODES * 8 + 255) / 256, 256>>>(b3, b1, out);
}

// round 13
// speedup vs baseline: 3.7914x; 1.0642x over previous
#include <cuda_runtime.h>
#include <cstdint>

// ---------------------------------------------------------------------------
// FAME_GCN. R13: split-merge decisive experiment, re-run with a SINGLE 100MB
// scratch (R12's 200MB static scratch appears to have tripped a module/memory
// guard -> all launches no-opped). Sequence: merge9 -> spmm(grp1) ->
// merge3 -> spmm(grp0). merge_kernel is a canonical phase-free stream:
// its DRAM% measures the true machine ceiling for this access pattern.
// ---------------------------------------------------------------------------

constexpr int N_NODES  = 5000;
constexpr int NFEAT    = 128;
constexpr int OUTC     = 16;
constexpr int TILE     = 64;
constexpr int PJ       = TILE + 1;                      // odd pitch: conflict-free
constexpr int NT       = (N_NODES + TILE - 1) / TILE;   // 79
constexpr int NTHREADS = 2 * TILE;                      // 128
constexpr int SLOTS    = TILE * (TILE / 4);             // 1024 float4 slots

// static scratch (no allocation allowed) — 100.6 MB total, <= proven R11 size
__device__ float g_T[(size_t)N_NODES * N_NODES];    // merged T (reused per group)
__device__ float g_s0[N_NODES * OUTC];
__device__ float g_s1[N_NODES * OUTC];
__device__ float g_acc0[N_NODES * OUTC];
__device__ float g_acc1[N_NODES * OUTC];

// ------------------------- PTX helpers -------------------------------------

__device__ __forceinline__ double pack2(float lo, float hi) {
    double d;
    asm("mov.b64 %0, {%1, %2};" : "=d"(d) : "f"(lo), "f"(hi));
    return d;
}

__device__ __forceinline__ double ffma2(double a, double b, double c) {
    double d;
    asm("fma.rn.f32x2 %0, %1, %2, %3;" : "=d"(d) : "d"(a), "d"(b), "d"(c));
    return d;
}

// ------------------------- phase-free streaming merge -----------------------

template<int K>
__global__ void __launch_bounds__(256) merge_kernel(const float* __restrict__ A,
                                                    const float* __restrict__ w) {
    const size_t NU = (size_t)N_NODES * N_NODES / 4;    // float4 units per plane
    float wk[K];
    #pragma unroll
    for (int k = 0; k < K; ++k) wk[k] = w[k];
    const float4* a4 = (const float4*)A;
    float4* t4 = (float4*)g_T;

    size_t i  = (size_t)blockIdx.x * 256 + threadIdx.x;
    size_t st = (size_t)gridDim.x * 256;
    for (; i < NU; i += st) {
        float4 a0 = make_float4(0.f, 0.f, 0.f, 0.f);
        float4 a1 = a0;
        #pragma unroll
        for (int k = 0; k < K; ++k) {
            float4 v = __ldcs(a4 + i + (size_t)k * NU);  // single-use: evict-first
            float4& a = (k & 1) ? a1 : a0;
            a.x = fmaf(wk[k], v.x, a.x);
            a.y = fmaf(wk[k], v.y, a.y);
            a.z = fmaf(wk[k], v.z, a.z);
            a.w = fmaf(wk[k], v.w, a.w);
        }
        float4 r = make_float4(a0.x + a1.x, a0.y + a1.y, a0.z + a1.z, a0.w + a1.w);
        __stcs(t4 + i, r);                               // streaming store
    }
}

// ------------------------- prep: support GEMMs + zero acc -------------------

__global__ void __launch_bounds__(256) prep_kernel(const float* __restrict__ feature,
                                                   const float* __restrict__ W3,
                                                   const float* __restrict__ W1) {
    __shared__ float Ws[2 * NFEAT * OUTC];
    int t = threadIdx.x;
    for (int q = t; q < NFEAT * OUTC; q += 256) {
        Ws[q] = W3[q];
        Ws[NFEAT * OUTC + q] = W1[q];
    }
    __syncthreads();

    int gid = blockIdx.x * 256 + t;
    int stride = gridDim.x * 256;

    for (int q = gid; q < N_NODES * OUTC; q += stride) {
        g_acc0[q] = 0.f;
        g_acc1[q] = 0.f;
    }

    for (int row = gid; row < 2 * N_NODES; row += stride) {
        int which = (row >= N_NODES) ? 1 : 0;
        int i = which ? row - N_NODES : row;
        const float4* f4 = (const float4*)(feature + (size_t)i * NFEAT);
        const float* Wp = Ws + which * (NFEAT * OUTC);
        float a[OUTC];
        #pragma unroll
        for (int c = 0; c < OUTC; ++c) a[c] = 0.f;
        #pragma unroll 4
        for (int k4 = 0; k4 < NFEAT / 4; ++k4) {
            float4 f = f4[k4];
            const float* w0 = Wp + (k4 * 4) * OUTC;
            #pragma unroll
            for (int c = 0; c < OUTC; ++c) {
                float v = fmaf(f.x, w0[c], 0.f);
                v = fmaf(f.y, w0[OUTC + c], v);
                v = fmaf(f.z, w0[2 * OUTC + c], v);
                v = fmaf(f.w, w0[3 * OUTC + c], v);
                a[c] += v;
            }
        }
        float* dst = (which ? g_s1 : g_s0) + (size_t)i * OUTC;
        #pragma unroll
        for (int c = 0; c < OUTC; ++c) dst[c] = a[c];
    }
}

// ------------------------- K=1 dual-pass SpMM tile --------------------------

__device__ __forceinline__ void spmm_tile(float* __restrict__ P,
                                          float* __restrict__ sC,
                                          float* __restrict__ sR,
                                          const float* __restrict__ s,
                                          float* __restrict__ acc,
                                          int r, int c) {
    int t = threadIdx.x;
    int gr0 = r * TILE, gc0 = c * TILE;

    // s tiles (zero-padded)
    {
        const float4* s4 = (const float4*)s;
        #pragma unroll
        for (int it = 0; it < (2 * TILE * OUTC / 4) / NTHREADS; ++it) {
            int q = t + it * NTHREADS;
            int half = q >> 8;
            int qq = q & 255;
            int j = qq >> 2, p = qq & 3;
            int gj = (half ? gr0 : gc0) + j;
            float4 v = make_float4(0.f, 0.f, 0.f, 0.f);
            if (gj < N_NODES) v = s4[gj * 4 + p];
            ((float4*)(half ? sR : sC))[qq] = v;
        }
    }

    // load merged tile
    #pragma unroll
    for (int it = 0; it < SLOTS / NTHREADS; ++it) {
        int q = t + it * NTHREADS;
        int row = q >> 4;
        int col = (q & 15) * 4;
        int gr = gr0 + row, gc = gc0 + col;
        float4 a = make_float4(0.f, 0.f, 0.f, 0.f);
        if (gr < N_NODES && gc < N_NODES)
            a = __ldcs((const float4*)(g_T + (size_t)gr * N_NODES + gc));
        float* d = P + row * PJ + col;
        d[0] = a.x; d[1] = a.y; d[2] = a.z; d[3] = a.w;
    }
    __syncthreads();

    // dual SpMM: t<64 row pass, t>=64 col pass
    double vacc[8];
    #pragma unroll
    for (int q = 0; q < 8; ++q) vacc[q] = 0.0;

    const float* mp;
    int mstride;
    const float* sv;
    if (t < TILE) { mp = P + t * PJ;     mstride = 1;  sv = sC; }
    else          { mp = P + (t - TILE); mstride = PJ; sv = sR; }

    #pragma unroll 4
    for (int j = 0; j < TILE; ++j) {
        float m = mp[j * mstride];
        double mm = pack2(m, m);
        const double2* s2 = (const double2*)(sv + j * OUTC);
        double2 a0 = s2[0], a1 = s2[1], a2 = s2[2], a3 = s2[3];
        vacc[0] = ffma2(mm, a0.x, vacc[0]);
        vacc[1] = ffma2(mm, a0.y, vacc[1]);
        vacc[2] = ffma2(mm, a1.x, vacc[2]);
        vacc[3] = ffma2(mm, a1.y, vacc[3]);
        vacc[4] = ffma2(mm, a2.x, vacc[4]);
        vacc[5] = ffma2(mm, a2.y, vacc[5]);
        vacc[6] = ffma2(mm, a3.x, vacc[6]);
        vacc[7] = ffma2(mm, a3.y, vacc[7]);
    }
    __syncthreads();    // reuse P as staging

    {
        float* base = P + (t < TILE ? t * OUTC : TILE * OUTC + (t - TILE) * OUTC);
        double* dst = (double*)base;
        #pragma unroll
        for (int q = 0; q < 8; ++q) dst[q] = vacc[q];
    }
    __syncthreads();

    if (t == 0) {
        asm volatile("fence.proxy.async.shared::cta;" ::: "memory");
        int rv = min(TILE, N_NODES - gr0);
        int cv = min(TILE, N_NODES - gc0);
        unsigned srR = (unsigned)__cvta_generic_to_shared(P);
        unsigned srC = (unsigned)__cvta_generic_to_shared(P + TILE * OUTC);
        asm volatile(
            "cp.reduce.async.bulk.global.shared::cta.bulk_group.add.f32 [%0], [%1], %2;"
            :: "l"(acc + (size_t)gr0 * OUTC), "r"(srR), "r"(rv * OUTC * 4) : "memory");
        asm volatile(
            "cp.reduce.async.bulk.global.shared::cta.bulk_group.add.f32 [%0], [%1], %2;"
            :: "l"(acc + (size_t)gc0 * OUTC), "r"(srC), "r"(cv * OUTC * 4) : "memory");
        asm volatile("cp.async.bulk.commit_group;" ::: "memory");
        asm volatile("cp.async.bulk.wait_group 0;" ::: "memory");
    }
}

template<int GRP>
__global__ void __launch_bounds__(NTHREADS) spmm_kernel() {
    __shared__ __align__(16) float P[TILE * PJ];
    __shared__ __align__(16) float sC[TILE * OUTC];
    __shared__ __align__(16) float sR[TILE * OUTC];

    int c = blockIdx.x;
    int r = blockIdx.y;
    if (GRP == 0) spmm_tile(P, sC, sR, g_s0, g_acc0, r, c);
    else          spmm_tile(P, sC, sR, g_s1, g_acc1, r, c);
}

// ------------------------- finalize ----------------------------------------

__global__ void __launch_bounds__(256) finalize_kernel(const float* __restrict__ b3,
                                                       const float* __restrict__ b1,
                                                       float* __restrict__ out) {
    int gid = blockIdx.x * 256 + threadIdx.x;
    if (gid < N_NODES * 2 * OUTC) {
        int i = gid >> 5;
        int c = gid & 31;
        float v;
        if (c < OUTC) v = g_acc0[i * OUTC + c] + b3[c];
        else          v = g_acc1[i * OUTC + (c - OUTC)] + b1[c - OUTC];
        out[gid] = v;
    }
}

// ------------------------- launch ------------------------------------------

extern "C" void kernel_launch(void* const* d_in, const int* in_sizes, int n_in,
                              void* d_out, int out_size) {
    const float* feature = (const float*)d_in[0];
    const float* A       = (const float*)d_in[1];
    const float* A_t     = (const float*)d_in[2];
    const float* w2      = (const float*)d_in[3];   // weight_b2 [3,1]
    const float* wb      = (const float*)d_in[4];   // weight_b  [9,1]
    const float* W3      = (const float*)d_in[5];
    const float* b3      = (const float*)d_in[6];
    const float* W1      = (const float*)d_in[7];
    const float* b1      = (const float*)d_in[8];
    float* out = (float*)d_out;

    prep_kernel<<<160, 256>>>(feature, W3, W1);

    dim3 grid(NT, NT);

    // group 1 (A_t, K=9): phase-free merge, then tile SpMM
    merge_kernel<9><<<1184, 256>>>(A_t, wb);
    spmm_kernel<1><<<grid, NTHREADS>>>();

    // group 0 (A, K=3)
    merge_kernel<3><<<1184, 256>>>(A, w2);
    spmm_kernel<0><<<grid, NTHREADS>>>();

    finalize_kernel<<<(N_NODES * 2 * OUTC + 255) / 256, 256>>>(b3, b1, out);
}